// round 4
// baseline (speedup 1.0000x reference)
#include <cuda_runtime.h>
#include <math.h>

#define Bb 256
#define Tt 256
#define Dd 64
#define Hh 512

typedef unsigned long long ull;

// Scratch (device globals: allocation-free rule).
__device__ float g_xp[(size_t)Bb * Tt * Hh];
__device__ float g_h [(size_t)Bb * Tt * Hh];

// ---------------- packed dual-fp32 helpers (sm_100+ f32x2) ----------------
__device__ __forceinline__ ull fma2(ull a, ull b, ull c) {
    ull d;
    asm("fma.rn.f32x2 %0, %1, %2, %3;" : "=l"(d) : "l"(a), "l"(b), "l"(c));
    return d;
}
__device__ __forceinline__ ull dup2(float x) {
    ull d;
    asm("mov.b64 %0, {%1, %2};" : "=l"(d) : "f"(x), "f"(x));
    return d;
}
__device__ __forceinline__ float2 unpack2(ull v) {
    float2 r;
    asm("mov.b64 {%0, %1}, %2;" : "=f"(r.x), "=f"(r.y) : "l"(v));
    return r;
}

#define CLUSTER_ARRIVE() asm volatile("barrier.cluster.arrive.aligned;" ::: "memory")
#define CLUSTER_WAIT()   asm volatile("barrier.cluster.wait.aligned;"   ::: "memory")

// ---------------------------------------------------------------------------
// Projection GEMM: out[M,Hh] = A[M,K] @ W[K,Hh] + bias    (M = Bb*Tt)
// Tile 128x128, BK=16, 256 threads, thread tile 8x8 via f32x2.  (unchanged R3)
// ---------------------------------------------------------------------------
template <int K>
__global__ __launch_bounds__(256) void proj_kernel(
    const float* __restrict__ A, const float* __restrict__ W,
    const float* __restrict__ bias, float* __restrict__ out)
{
    __shared__ float sA[16 * 132];
    __shared__ float sB[16 * 128];

    const int n0 = blockIdx.x * 128;
    const int m0 = blockIdx.y * 128;
    const int tid = threadIdx.x;
    const int tx = tid & 15;
    const int ty = tid >> 4;

    const int arow = tid >> 1;
    const int ak   = (tid & 1) * 8;
    const int bk   = tid >> 4;
    const int bc   = (tid & 15) * 8;

    ull acc[8][4];
#pragma unroll
    for (int i = 0; i < 8; i++)
#pragma unroll
        for (int j = 0; j < 4; j++) acc[i][j] = 0ull;

    float4 va0 = *(const float4*)&A[(size_t)(m0 + arow) * K + ak];
    float4 va1 = *(const float4*)&A[(size_t)(m0 + arow) * K + ak + 4];
    float4 vb0 = *(const float4*)&W[(size_t)bk * Hh + n0 + bc];
    float4 vb1 = *(const float4*)&W[(size_t)bk * Hh + n0 + bc + 4];

    const int NB = K / 16;
    for (int kb = 0; kb < NB; kb++) {
        sA[(ak + 0) * 132 + arow] = va0.x;
        sA[(ak + 1) * 132 + arow] = va0.y;
        sA[(ak + 2) * 132 + arow] = va0.z;
        sA[(ak + 3) * 132 + arow] = va0.w;
        sA[(ak + 4) * 132 + arow] = va1.x;
        sA[(ak + 5) * 132 + arow] = va1.y;
        sA[(ak + 6) * 132 + arow] = va1.z;
        sA[(ak + 7) * 132 + arow] = va1.w;
        *(float4*)&sB[bk * 128 + bc]     = vb0;
        *(float4*)&sB[bk * 128 + bc + 4] = vb1;
        __syncthreads();

        if (kb + 1 < NB) {
            int k0 = (kb + 1) * 16;
            va0 = *(const float4*)&A[(size_t)(m0 + arow) * K + k0 + ak];
            va1 = *(const float4*)&A[(size_t)(m0 + arow) * K + k0 + ak + 4];
            vb0 = *(const float4*)&W[(size_t)(k0 + bk) * Hh + n0 + bc];
            vb1 = *(const float4*)&W[(size_t)(k0 + bk) * Hh + n0 + bc + 4];
        }

#pragma unroll
        for (int kk = 0; kk < 16; kk++) {
            float4 a0 = *(const float4*)&sA[kk * 132 + ty * 8];
            float4 a1 = *(const float4*)&sA[kk * 132 + ty * 8 + 4];
            ulonglong2 b0 = *(const ulonglong2*)&sB[kk * 128 + tx * 8];
            ulonglong2 b1 = *(const ulonglong2*)&sB[kk * 128 + tx * 8 + 4];
            float ar[8] = {a0.x, a0.y, a0.z, a0.w, a1.x, a1.y, a1.z, a1.w};
#pragma unroll
            for (int r = 0; r < 8; r++) {
                ull av = dup2(ar[r]);
                acc[r][0] = fma2(av, b0.x, acc[r][0]);
                acc[r][1] = fma2(av, b0.y, acc[r][1]);
                acc[r][2] = fma2(av, b1.x, acc[r][2]);
                acc[r][3] = fma2(av, b1.y, acc[r][3]);
            }
        }
        __syncthreads();
    }

    float4 bi0 = *(const float4*)&bias[n0 + tx * 8];
    float4 bi1 = *(const float4*)&bias[n0 + tx * 8 + 4];
#pragma unroll
    for (int r = 0; r < 8; r++) {
        float2 u0 = unpack2(acc[r][0]);
        float2 u1 = unpack2(acc[r][1]);
        float2 u2 = unpack2(acc[r][2]);
        float2 u3 = unpack2(acc[r][3]);
        float4 o0, o1;
        o0.x = u0.x + bi0.x; o0.y = u0.y + bi0.y; o0.z = u1.x + bi0.z; o0.w = u1.y + bi0.w;
        o1.x = u2.x + bi1.x; o1.y = u2.y + bi1.y; o1.z = u3.x + bi1.z; o1.w = u3.y + bi1.w;
        size_t base = (size_t)(m0 + ty * 8 + r) * Hh + n0 + tx * 8;
        *(float4*)&out[base]     = o0;
        *(float4*)&out[base + 4] = o1;
    }
}

// ---------------------------------------------------------------------------
// Persistent layer kernel (cluster version).
// Grid (8 col-tiles x 16 batch-groups); cluster = 8 CTAs of one batch group.
// Wh slice [512x64] SMEM-resident. CTA-cooperative h staging (R2 style,
// SH_STR=514 conflict-free), split-k(8) + smem reduction into a SEPARATE
// partials region. Sync per step: cluster barrier + 2 syncthreads.
// ---------------------------------------------------------------------------
#define SH_STR  514
#define RED_STR 66
#define WREG    (16 * RED_STR)               // 1056 floats per warp partials
#define SW_FLOATS  (512 * 64)                // 32768
#define SH_FLOATS  (16 * SH_STR)             // 8224
#define RED_FLOATS (8 * WREG)                // 8448
#define LAYER_SMEM ((SW_FLOATS + SH_FLOATS + RED_FLOATS) * 4)   // ~193 KB

extern __shared__ float s_mem[];

__global__ __launch_bounds__(256, 1) __cluster_dims__(8, 1, 1)
void layer_kernel(const float* __restrict__ xp, const float* __restrict__ Wh,
                  float* __restrict__ h)
{
    float* sW   = s_mem;                       // [512][64]
    float* sH   = s_mem + SW_FLOATS;           // [16][514]
    float* sRed = s_mem + SW_FLOATS + SH_FLOATS;

    const int n0 = blockIdx.x * 64;
    const int b0 = blockIdx.y * 16;

    const int tid  = threadIdx.x;
    const int w    = tid >> 5;
    const int lane = tid & 31;
    const int rg   = lane >> 3;          // 4 row groups (of 4 rows)
    const int cg   = lane & 7;           // 8 col groups
    const int kbase = w * 64;
    const int tx = tid & 15;             // epilogue col group of 4
    const int ty = tid >> 4;             // epilogue batch row

    // ---- stage Wh[:, n0:n0+64] once ----
    for (int i = tid; i < 512 * 16; i += 256) {
        int k = i >> 4, c4 = i & 15;
        float4 v = *(const float4*)&Wh[(size_t)k * Hh + n0 + c4 * 4];
        *(float4*)&sW[k * 64 + c4 * 4] = v;
    }

    // ---- t = 0: h0 = tanh(xp0) ----
    {
        size_t base = ((size_t)(b0 + ty) * Tt) * Hh + n0 + tx * 4;
        float4 xv = *(const float4*)&xp[base];
        float4 o;
        o.x = tanhf(xv.x); o.y = tanhf(xv.y); o.z = tanhf(xv.z); o.w = tanhf(xv.w);
        *(float4*)&h[base] = o;
    }
    __syncthreads();            // sW staged + h0 stores issued
    CLUSTER_ARRIVE();           // release h0 to cluster peers

    for (int t = 1; t < Tt; t++) {
        // prefetch xp for this step (independent of peers)
        size_t obase = (((size_t)(b0 + ty) * Tt) + t) * Hh + n0 + tx * 4;
        float4 xv = *(const float4*)&xp[obase];

        CLUSTER_WAIT();         // acquire: all peers' h_{t-1} visible

        // ---- CTA-cooperative stage of h_{t-1}[b0..b0+15, :] ----
        float4 sv[8];
#pragma unroll
        for (int j = 0; j < 8; j++) {
            int idx = tid + j * 256;
            int b = idx >> 7, k4 = idx & 127;
            sv[j] = *(const float4*)&h[(((size_t)(b0 + b) * Tt) + (t - 1)) * Hh + k4 * 4];
        }
#pragma unroll
        for (int j = 0; j < 8; j++) {
            int idx = tid + j * 256;
            int b = idx >> 7, k4 = idx & 127;
            float* d = &sH[b * SH_STR + k4 * 4];
            *(float2*)&d[0] = make_float2(sv[j].x, sv[j].y);
            *(float2*)&d[2] = make_float2(sv[j].z, sv[j].w);
        }
        __syncthreads();

        // ---- split-k compute: warp w does k in [kbase, kbase+64) ----
        ull acc[4][4];
#pragma unroll
        for (int i = 0; i < 4; i++)
#pragma unroll
            for (int j = 0; j < 4; j++) acc[i][j] = 0ull;

        const float* hp = &sH[(rg * 4) * SH_STR + kbase];
        const float* wp = &sW[kbase * 64];
#pragma unroll 4
        for (int kk = 0; kk < 64; kk++) {
            ull a0 = dup2(hp[kk]);
            ull a1 = dup2(hp[SH_STR + kk]);
            ull a2 = dup2(hp[2 * SH_STR + kk]);
            ull a3 = dup2(hp[3 * SH_STR + kk]);
            ulonglong2 wlo = *(const ulonglong2*)&wp[kk * 64 + cg * 4];
            ulonglong2 whi = *(const ulonglong2*)&wp[kk * 64 + 32 + cg * 4];
            acc[0][0] = fma2(a0, wlo.x, acc[0][0]); acc[0][1] = fma2(a0, wlo.y, acc[0][1]);
            acc[0][2] = fma2(a0, whi.x, acc[0][2]); acc[0][3] = fma2(a0, whi.y, acc[0][3]);
            acc[1][0] = fma2(a1, wlo.x, acc[1][0]); acc[1][1] = fma2(a1, wlo.y, acc[1][1]);
            acc[1][2] = fma2(a1, whi.x, acc[1][2]); acc[1][3] = fma2(a1, whi.y, acc[1][3]);
            acc[2][0] = fma2(a2, wlo.x, acc[2][0]); acc[2][1] = fma2(a2, wlo.y, acc[2][1]);
            acc[2][2] = fma2(a2, whi.x, acc[2][2]); acc[2][3] = fma2(a2, whi.y, acc[2][3]);
            acc[3][0] = fma2(a3, wlo.x, acc[3][0]); acc[3][1] = fma2(a3, wlo.y, acc[3][1]);
            acc[3][2] = fma2(a3, whi.x, acc[3][2]); acc[3][3] = fma2(a3, whi.y, acc[3][3]);
        }

        // ---- store partials (own region — no barrier needed before) ----
#pragma unroll
        for (int j = 0; j < 4; j++) {
            float* dst = &sRed[w * WREG + (rg * 4 + j) * RED_STR];
            *(ull*)&dst[cg * 4]          = acc[j][0];
            *(ull*)&dst[cg * 4 + 2]      = acc[j][1];
            *(ull*)&dst[32 + cg * 4]     = acc[j][2];
            *(ull*)&dst[32 + cg * 4 + 2] = acc[j][3];
        }
        __syncthreads();

        // ---- reduce 8 partials, add xp, tanh, store h_t ----
        {
            float2 s0 = make_float2(0.f, 0.f), s1 = make_float2(0.f, 0.f);
            int rbase = ty * RED_STR + tx * 4;
#pragma unroll
            for (int w2 = 0; w2 < 8; w2++) {
                float2 u0 = unpack2(*(const ull*)&sRed[w2 * WREG + rbase]);
                float2 u1 = unpack2(*(const ull*)&sRed[w2 * WREG + rbase + 2]);
                s0.x += u0.x; s0.y += u0.y; s1.x += u1.x; s1.y += u1.y;
            }
            float4 o;
            o.x = tanhf(s0.x + xv.x); o.y = tanhf(s0.y + xv.y);
            o.z = tanhf(s1.x + xv.z); o.w = tanhf(s1.y + xv.w);
            *(float4*)&h[obase] = o;
        }

        if (t < Tt - 1) CLUSTER_ARRIVE();   // release h_t (balanced with waits)
    }
}

// ---------------------------------------------------------------------------
// Final: out[b] = h[b, T-1, :] @ Wf + bf
// ---------------------------------------------------------------------------
__global__ void final_kernel(const float* __restrict__ h, const float* __restrict__ Wf,
                             const float* __restrict__ bf, float* __restrict__ out)
{
    int b = blockIdx.x;
    const float* row = h + ((size_t)b * Tt + (Tt - 1)) * Hh;
    float s = 0.f;
    for (int j = threadIdx.x; j < Hh; j += 128) s += row[j] * Wf[j];
#pragma unroll
    for (int o = 16; o > 0; o >>= 1) s += __shfl_down_sync(0xffffffffu, s, o);
    __shared__ float ws[4];
    if ((threadIdx.x & 31) == 0) ws[threadIdx.x >> 5] = s;
    __syncthreads();
    if (threadIdx.x == 0) out[b] = ws[0] + ws[1] + ws[2] + ws[3] + bf[0];
}

// ---------------------------------------------------------------------------
extern "C" void kernel_launch(void* const* d_in, const int* in_sizes, int n_in,
                              void* d_out, int out_size)
{
    const float* x   = (const float*)d_in[0];
    const float* Wx0 = (const float*)d_in[1];
    const float* Wh0 = (const float*)d_in[2];
    const float* b0  = (const float*)d_in[3];
    const float* Wx1 = (const float*)d_in[4];
    const float* Wh1 = (const float*)d_in[5];
    const float* b1  = (const float*)d_in[6];
    const float* Wx2 = (const float*)d_in[7];
    const float* Wh2 = (const float*)d_in[8];
    const float* b2  = (const float*)d_in[9];
    const float* Wf  = (const float*)d_in[10];
    const float* bf  = (const float*)d_in[11];
    float* out = (float*)d_out;

    void* p;
    cudaGetSymbolAddress(&p, g_xp);
    float* xp = (float*)p;
    cudaGetSymbolAddress(&p, g_h);
    float* hb = (float*)p;

    cudaFuncSetAttribute(layer_kernel, cudaFuncAttributeMaxDynamicSharedMemorySize, LAYER_SMEM);

    dim3 pgrid(Hh / 128, (Bb * Tt) / 128);   // (4, 512)
    dim3 lgrid(Hh / 64, Bb / 16);            // (8, 16): 16 clusters of 8 CTAs

    proj_kernel<Dd><<<pgrid, 256>>>(x, Wx0, b0, xp);
    layer_kernel<<<lgrid, 256, LAYER_SMEM>>>(xp, Wh0, hb);

    proj_kernel<Hh><<<pgrid, 256>>>(hb, Wx1, b1, xp);
    layer_kernel<<<lgrid, 256, LAYER_SMEM>>>(xp, Wh1, hb);

    proj_kernel<Hh><<<pgrid, 256>>>(hb, Wx2, b2, xp);
    layer_kernel<<<lgrid, 256, LAYER_SMEM>>>(xp, Wh2, hb);

    final_kernel<<<Bb, 128>>>(hb, Wf, bf, out);
}

// round 5
// speedup vs baseline: 1.2676x; 1.2676x over previous
#include <cuda_runtime.h>
#include <math.h>

#define Bb 256
#define Tt 256
#define Dd 64
#define Hh 512

typedef unsigned long long ull;

// Scratch (device globals: allocation-free rule).
__device__ float g_xp[(size_t)Bb * Tt * Hh];
__device__ float g_h [(size_t)Bb * Tt * Hh];
__device__ int   g_bar[3 * 32];          // per (layer, batch-group of 8) counters

// ---------------- packed dual-fp32 helpers (sm_100+ f32x2) ----------------
__device__ __forceinline__ ull fma2(ull a, ull b, ull c) {
    ull d;
    asm("fma.rn.f32x2 %0, %1, %2, %3;" : "=l"(d) : "l"(a), "l"(b), "l"(c));
    return d;
}
__device__ __forceinline__ ull dup2(float x) {
    ull d;
    asm("mov.b64 %0, {%1, %2};" : "=l"(d) : "f"(x), "f"(x));
    return d;
}
__device__ __forceinline__ float2 unpack2(ull v) {
    float2 r;
    asm("mov.b64 {%0, %1}, %2;" : "=f"(r.x), "=f"(r.y) : "l"(v));
    return r;
}
__device__ __forceinline__ int ld_acquire(const int* p) {
    int v;
    asm volatile("ld.acquire.gpu.global.b32 %0, [%1];" : "=r"(v) : "l"(p));
    return v;
}
__device__ __forceinline__ void red_release_add(int* p, int v) {
    asm volatile("red.release.gpu.global.add.s32 [%0], %1;" :: "l"(p), "r"(v) : "memory");
}

__global__ void zero_bar_kernel() {
    if (threadIdx.x < 96) g_bar[threadIdx.x] = 0;
}

// ---------------------------------------------------------------------------
// Projection GEMM: out[M,Hh] = A[M,K] @ W[K,Hh] + bias    (M = Bb*Tt)
// Tile 128x128, BK=16, 256 threads, thread tile 8x8 via f32x2.
// ---------------------------------------------------------------------------
template <int K>
__global__ __launch_bounds__(256) void proj_kernel(
    const float* __restrict__ A, const float* __restrict__ W,
    const float* __restrict__ bias, float* __restrict__ out)
{
    __shared__ float sA[16 * 132];
    __shared__ float sB[16 * 128];

    const int n0 = blockIdx.x * 128;
    const int m0 = blockIdx.y * 128;
    const int tid = threadIdx.x;
    const int tx = tid & 15;
    const int ty = tid >> 4;

    const int arow = tid >> 1;
    const int ak   = (tid & 1) * 8;
    const int bk   = tid >> 4;
    const int bc   = (tid & 15) * 8;

    ull acc[8][4];
#pragma unroll
    for (int i = 0; i < 8; i++)
#pragma unroll
        for (int j = 0; j < 4; j++) acc[i][j] = 0ull;

    float4 va0 = *(const float4*)&A[(size_t)(m0 + arow) * K + ak];
    float4 va1 = *(const float4*)&A[(size_t)(m0 + arow) * K + ak + 4];
    float4 vb0 = *(const float4*)&W[(size_t)bk * Hh + n0 + bc];
    float4 vb1 = *(const float4*)&W[(size_t)bk * Hh + n0 + bc + 4];

    const int NB = K / 16;
    for (int kb = 0; kb < NB; kb++) {
        sA[(ak + 0) * 132 + arow] = va0.x;
        sA[(ak + 1) * 132 + arow] = va0.y;
        sA[(ak + 2) * 132 + arow] = va0.z;
        sA[(ak + 3) * 132 + arow] = va0.w;
        sA[(ak + 4) * 132 + arow] = va1.x;
        sA[(ak + 5) * 132 + arow] = va1.y;
        sA[(ak + 6) * 132 + arow] = va1.z;
        sA[(ak + 7) * 132 + arow] = va1.w;
        *(float4*)&sB[bk * 128 + bc]     = vb0;
        *(float4*)&sB[bk * 128 + bc + 4] = vb1;
        __syncthreads();

        if (kb + 1 < NB) {
            int k0 = (kb + 1) * 16;
            va0 = *(const float4*)&A[(size_t)(m0 + arow) * K + k0 + ak];
            va1 = *(const float4*)&A[(size_t)(m0 + arow) * K + k0 + ak + 4];
            vb0 = *(const float4*)&W[(size_t)(k0 + bk) * Hh + n0 + bc];
            vb1 = *(const float4*)&W[(size_t)(k0 + bk) * Hh + n0 + bc + 4];
        }

#pragma unroll
        for (int kk = 0; kk < 16; kk++) {
            float4 a0 = *(const float4*)&sA[kk * 132 + ty * 8];
            float4 a1 = *(const float4*)&sA[kk * 132 + ty * 8 + 4];
            ulonglong2 b0 = *(const ulonglong2*)&sB[kk * 128 + tx * 8];
            ulonglong2 b1 = *(const ulonglong2*)&sB[kk * 128 + tx * 8 + 4];
            float ar[8] = {a0.x, a0.y, a0.z, a0.w, a1.x, a1.y, a1.z, a1.w};
#pragma unroll
            for (int r = 0; r < 8; r++) {
                ull av = dup2(ar[r]);
                acc[r][0] = fma2(av, b0.x, acc[r][0]);
                acc[r][1] = fma2(av, b0.y, acc[r][1]);
                acc[r][2] = fma2(av, b1.x, acc[r][2]);
                acc[r][3] = fma2(av, b1.y, acc[r][3]);
            }
        }
        __syncthreads();
    }

    float4 bi0 = *(const float4*)&bias[n0 + tx * 8];
    float4 bi1 = *(const float4*)&bias[n0 + tx * 8 + 4];
#pragma unroll
    for (int r = 0; r < 8; r++) {
        float2 u0 = unpack2(acc[r][0]);
        float2 u1 = unpack2(acc[r][1]);
        float2 u2 = unpack2(acc[r][2]);
        float2 u3 = unpack2(acc[r][3]);
        float4 o0, o1;
        o0.x = u0.x + bi0.x; o0.y = u0.y + bi0.y; o0.z = u1.x + bi0.z; o0.w = u1.y + bi0.w;
        o1.x = u2.x + bi1.x; o1.y = u2.y + bi1.y; o1.z = u3.x + bi1.z; o1.w = u3.y + bi1.w;
        size_t base = (size_t)(m0 + ty * 8 + r) * Hh + n0 + tx * 8;
        *(float4*)&out[base]     = o0;
        *(float4*)&out[base + 4] = o1;
    }
}

// ---------------------------------------------------------------------------
// Persistent layer kernel: 32 batch-groups of 8 rows; each CTA serves TWO
// groups (A = 2*by, B = 2*by+1) and alternates subtasks each step so the
// inter-CTA sync tail of one group hides behind the other group's compute.
// Grid (8 col-slices x 16 pairs) = 128 CTAs. Wh slice [512x64] SMEM-resident.
// ---------------------------------------------------------------------------
#define SH_STR   516                      // 8B/16B aligned, banks {0,8,16,24}
#define RED_STR  66
#define WREG     (8 * RED_STR)            // 528 floats per warp partials
#define SW_FLOATS  (512 * 64)             // 32768
#define SH_FLOATS  (8 * SH_STR)           // 4128
#define RED_FLOATS (8 * WREG)             // 4224
#define LAYER_SMEM ((SW_FLOATS + SH_FLOATS + RED_FLOATS) * 4)   // ~160.6 KB

extern __shared__ float s_mem[];

struct SubCtx {
    const float* xp; float* h;
    int n0, tid, w, lane, rg, cg, kbase;
};

__device__ __forceinline__ void do_subtask(
    const SubCtx& c, float* sW, float* sH, float* sRed,
    int gb, int t, int* cnt)
{
    // prefetch xp (independent of flag)
    const int row = c.tid >> 5;
    const int c2  = (c.tid & 31) * 2;
    size_t obase = (((size_t)(gb + row) * Tt) + t) * Hh + c.n0 + c2;
    float2 xv = *(const float2*)&c.xp[obase];

    // wait for h_{t-1} of this group
    if (c.tid == 0) {
        while (ld_acquire(cnt) < 8 * t) { }
    }
    __syncthreads();

    // stage h_{t-1}[gb..gb+7, :] (16 KB)
#pragma unroll
    for (int j = 0; j < 4; j++) {
        int idx = c.tid + j * 256;
        int b = idx >> 7, k4 = idx & 127;
        float4 v = *(const float4*)&c.h[(((size_t)(gb + b) * Tt) + (t - 1)) * Hh + k4 * 4];
        *(float4*)&sH[b * SH_STR + k4 * 4] = v;   // SH_STR%4==0 -> aligned
    }
    __syncthreads();

    // split-k compute: warp w does k in [kbase, kbase+64), tile [8 x 64]
    ull a00 = 0, a01 = 0, a02 = 0, a03 = 0;
    ull a10 = 0, a11 = 0, a12 = 0, a13 = 0;
    const int r0 = c.rg * 2, r1 = r0 + 1;
    const float* hp0 = &sH[r0 * SH_STR + c.kbase];
    const float* hp1 = &sH[r1 * SH_STR + c.kbase];
    const float* wp  = &sW[c.kbase * 64];
#pragma unroll 4
    for (int kk2 = 0; kk2 < 32; kk2++) {
        int k = kk2 * 2;
        float2 h0 = *(const float2*)&hp0[k];
        float2 h1 = *(const float2*)&hp1[k];
        ulonglong2 w0lo = *(const ulonglong2*)&wp[k * 64 + c.cg * 4];
        ulonglong2 w0hi = *(const ulonglong2*)&wp[k * 64 + 32 + c.cg * 4];
        ulonglong2 w1lo = *(const ulonglong2*)&wp[(k + 1) * 64 + c.cg * 4];
        ulonglong2 w1hi = *(const ulonglong2*)&wp[(k + 1) * 64 + 32 + c.cg * 4];
        ull a;
        a = dup2(h0.x);
        a00 = fma2(a, w0lo.x, a00); a01 = fma2(a, w0lo.y, a01);
        a02 = fma2(a, w0hi.x, a02); a03 = fma2(a, w0hi.y, a03);
        a = dup2(h1.x);
        a10 = fma2(a, w0lo.x, a10); a11 = fma2(a, w0lo.y, a11);
        a12 = fma2(a, w0hi.x, a12); a13 = fma2(a, w0hi.y, a13);
        a = dup2(h0.y);
        a00 = fma2(a, w1lo.x, a00); a01 = fma2(a, w1lo.y, a01);
        a02 = fma2(a, w1hi.x, a02); a03 = fma2(a, w1hi.y, a03);
        a = dup2(h1.y);
        a10 = fma2(a, w1lo.x, a10); a11 = fma2(a, w1lo.y, a11);
        a12 = fma2(a, w1hi.x, a12); a13 = fma2(a, w1hi.y, a13);
    }

    // store partials (own region, no pre-barrier)
    {
        float* d0 = &sRed[c.w * WREG + r0 * RED_STR];
        float* d1 = &sRed[c.w * WREG + r1 * RED_STR];
        *(ull*)&d0[c.cg * 4]          = a00;
        *(ull*)&d0[c.cg * 4 + 2]      = a01;
        *(ull*)&d0[32 + c.cg * 4]     = a02;
        *(ull*)&d0[32 + c.cg * 4 + 2] = a03;
        *(ull*)&d1[c.cg * 4]          = a10;
        *(ull*)&d1[c.cg * 4 + 2]      = a11;
        *(ull*)&d1[32 + c.cg * 4]     = a12;
        *(ull*)&d1[32 + c.cg * 4 + 2] = a13;
    }
    __syncthreads();

    // reduce 8 partials, add xp, tanh, store h_t
    {
        float2 s = make_float2(0.f, 0.f);
        int rbase = row * RED_STR + c2;
#pragma unroll
        for (int w2 = 0; w2 < 8; w2++) {
            float2 u = unpack2(*(const ull*)&sRed[w2 * WREG + rbase]);
            s.x += u.x; s.y += u.y;
        }
        float2 o;
        o.x = tanhf(s.x + xv.x);
        o.y = tanhf(s.y + xv.y);
        *(float2*)&c.h[obase] = o;
    }
    __syncthreads();                     // STGs happen-before the release below
    if (c.tid == 0 && t < Tt - 1) red_release_add(cnt, 1);
}

__global__ __launch_bounds__(256, 1) void layer_kernel(
    const float* __restrict__ xp, const float* __restrict__ Wh,
    float* __restrict__ h, int* __restrict__ bar, int layer)
{
    float* sW   = s_mem;                          // [512][64]
    float* sH   = s_mem + SW_FLOATS;              // [8][516]
    float* sRed = s_mem + SW_FLOATS + SH_FLOATS;  // [8][8][66]

    SubCtx c;
    c.xp = xp; c.h = h;
    c.n0   = blockIdx.x * 64;
    c.tid  = threadIdx.x;
    c.w    = c.tid >> 5;
    c.lane = c.tid & 31;
    c.rg   = c.lane >> 3;
    c.cg   = c.lane & 7;
    c.kbase = c.w * 64;

    const int gA = 2 * blockIdx.y, gB = gA + 1;
    const int gbA = gA * 8, gbB = gB * 8;
    int* cntA = &bar[layer * 32 + gA];
    int* cntB = &bar[layer * 32 + gB];

    // ---- stage Wh[:, n0:n0+64] once ----
    for (int i = c.tid; i < 512 * 16; i += 256) {
        int k = i >> 4, c4 = i & 15;
        float4 v = *(const float4*)&Wh[(size_t)k * Hh + c.n0 + c4 * 4];
        *(float4*)&sW[k * 64 + c4 * 4] = v;
    }

    // ---- t = 0: h0 = tanh(xp0) for both groups ----
    {
        const int row = c.tid >> 5;
        const int c2  = (c.tid & 31) * 2;
        size_t baseA = ((size_t)(gbA + row) * Tt) * Hh + c.n0 + c2;
        size_t baseB = ((size_t)(gbB + row) * Tt) * Hh + c.n0 + c2;
        float2 xa = *(const float2*)&xp[baseA];
        float2 xb = *(const float2*)&xp[baseB];
        float2 oa, ob;
        oa.x = tanhf(xa.x); oa.y = tanhf(xa.y);
        ob.x = tanhf(xb.x); ob.y = tanhf(xb.y);
        *(float2*)&h[baseA] = oa;
        *(float2*)&h[baseB] = ob;
    }
    __syncthreads();              // covers sW staging + h0 stores
    if (c.tid == 0) {
        red_release_add(cntA, 1);
        red_release_add(cntB, 1);
    }

    for (int t = 1; t < Tt; t++) {
        do_subtask(c, sW, sH, sRed, gbA, t, cntA);
        do_subtask(c, sW, sH, sRed, gbB, t, cntB);
    }
}

// ---------------------------------------------------------------------------
// Final: out[b] = h[b, T-1, :] @ Wf + bf
// ---------------------------------------------------------------------------
__global__ void final_kernel(const float* __restrict__ h, const float* __restrict__ Wf,
                             const float* __restrict__ bf, float* __restrict__ out)
{
    int b = blockIdx.x;
    const float* row = h + ((size_t)b * Tt + (Tt - 1)) * Hh;
    float s = 0.f;
    for (int j = threadIdx.x; j < Hh; j += 128) s += row[j] * Wf[j];
#pragma unroll
    for (int o = 16; o > 0; o >>= 1) s += __shfl_down_sync(0xffffffffu, s, o);
    __shared__ float ws[4];
    if ((threadIdx.x & 31) == 0) ws[threadIdx.x >> 5] = s;
    __syncthreads();
    if (threadIdx.x == 0) out[b] = ws[0] + ws[1] + ws[2] + ws[3] + bf[0];
}

// ---------------------------------------------------------------------------
extern "C" void kernel_launch(void* const* d_in, const int* in_sizes, int n_in,
                              void* d_out, int out_size)
{
    const float* x   = (const float*)d_in[0];
    const float* Wx0 = (const float*)d_in[1];
    const float* Wh0 = (const float*)d_in[2];
    const float* b0  = (const float*)d_in[3];
    const float* Wx1 = (const float*)d_in[4];
    const float* Wh1 = (const float*)d_in[5];
    const float* b1  = (const float*)d_in[6];
    const float* Wx2 = (const float*)d_in[7];
    const float* Wh2 = (const float*)d_in[8];
    const float* b2  = (const float*)d_in[9];
    const float* Wf  = (const float*)d_in[10];
    const float* bf  = (const float*)d_in[11];
    float* out = (float*)d_out;

    void* p;
    cudaGetSymbolAddress(&p, g_xp);
    float* xp = (float*)p;
    cudaGetSymbolAddress(&p, g_h);
    float* hb = (float*)p;
    cudaGetSymbolAddress(&p, g_bar);
    int* bar = (int*)p;

    cudaFuncSetAttribute(layer_kernel, cudaFuncAttributeMaxDynamicSharedMemorySize, LAYER_SMEM);

    dim3 pgrid(Hh / 128, (Bb * Tt) / 128);   // (4, 512)
    dim3 lgrid(Hh / 64, Bb / 16);            // (8, 16) = 128 CTAs

    zero_bar_kernel<<<1, 128>>>();

    proj_kernel<Dd><<<pgrid, 256>>>(x, Wx0, b0, xp);
    layer_kernel<<<lgrid, 256, LAYER_SMEM>>>(xp, Wh0, hb, bar, 0);

    proj_kernel<Hh><<<pgrid, 256>>>(hb, Wx1, b1, xp);
    layer_kernel<<<lgrid, 256, LAYER_SMEM>>>(xp, Wh1, hb, bar, 1);

    proj_kernel<Hh><<<pgrid, 256>>>(hb, Wx2, b2, xp);
    layer_kernel<<<lgrid, 256, LAYER_SMEM>>>(xp, Wh2, hb, bar, 2);

    final_kernel<<<Bb, 128>>>(hb, Wf, bf, out);
}

// round 6
// speedup vs baseline: 1.5851x; 1.2505x over previous
#include <cuda_runtime.h>
#include <math.h>

#define Bb 256
#define Tt 256
#define Dd 64
#define Hh 512

typedef unsigned long long ull;

// Scratch (device globals: allocation-free rule).
__device__ float g_xp[(size_t)Bb * Tt * Hh];
__device__ float g_h [(size_t)Bb * Tt * Hh];
__device__ float g_hx[2 * Bb * Hh];      // 1MB L2-hot exchange buffer (double)
__device__ int   g_bar[3 * 16];          // per (layer, batch-group) counters

// ---------------- packed dual-fp32 helpers (sm_100+ f32x2) ----------------
__device__ __forceinline__ ull fma2(ull a, ull b, ull c) {
    ull d;
    asm("fma.rn.f32x2 %0, %1, %2, %3;" : "=l"(d) : "l"(a), "l"(b), "l"(c));
    return d;
}
__device__ __forceinline__ ull dup2(float x) {
    ull d;
    asm("mov.b64 %0, {%1, %2};" : "=l"(d) : "f"(x), "f"(x));
    return d;
}
__device__ __forceinline__ float2 unpack2(ull v) {
    float2 r;
    asm("mov.b64 {%0, %1}, %2;" : "=f"(r.x), "=f"(r.y) : "l"(v));
    return r;
}
__device__ __forceinline__ int ld_acquire(const int* p) {
    int v;
    asm volatile("ld.acquire.gpu.global.b32 %0, [%1];" : "=r"(v) : "l"(p));
    return v;
}
__device__ __forceinline__ void red_release_add(int* p, int v) {
    asm volatile("red.release.gpu.global.add.s32 [%0], %1;" :: "l"(p), "r"(v) : "memory");
}
// fast tanh: 1 - 2/(1+e^{2|x|}), MUFU EX2 + fast div.  abs err ~3e-7.
__device__ __forceinline__ float fast_tanh(float x) {
    float ax = fabsf(x);
    float e;
    asm("ex2.approx.f32 %0, %1;" : "=f"(e) : "f"(ax * 2.885390082f));
    float t = 1.0f - __fdividef(2.0f, e + 1.0f);
    return copysignf(t, x);
}

__global__ void zero_bar_kernel() {
    if (threadIdx.x < 48) g_bar[threadIdx.x] = 0;
}

// ---------------------------------------------------------------------------
// Projection GEMM: out[M,Hh] = A[M,K] @ W[K,Hh] + bias    (M = Bb*Tt)
// Tile 128x128, BK=16, 256 threads, thread tile 8x8 via f32x2.  (proven R3)
// ---------------------------------------------------------------------------
template <int K>
__global__ __launch_bounds__(256) void proj_kernel(
    const float* __restrict__ A, const float* __restrict__ W,
    const float* __restrict__ bias, float* __restrict__ out)
{
    __shared__ float sA[16 * 132];
    __shared__ float sB[16 * 128];

    const int n0 = blockIdx.x * 128;
    const int m0 = blockIdx.y * 128;
    const int tid = threadIdx.x;
    const int tx = tid & 15;
    const int ty = tid >> 4;

    const int arow = tid >> 1;
    const int ak   = (tid & 1) * 8;
    const int bk   = tid >> 4;
    const int bc   = (tid & 15) * 8;

    ull acc[8][4];
#pragma unroll
    for (int i = 0; i < 8; i++)
#pragma unroll
        for (int j = 0; j < 4; j++) acc[i][j] = 0ull;

    float4 va0 = *(const float4*)&A[(size_t)(m0 + arow) * K + ak];
    float4 va1 = *(const float4*)&A[(size_t)(m0 + arow) * K + ak + 4];
    float4 vb0 = *(const float4*)&W[(size_t)bk * Hh + n0 + bc];
    float4 vb1 = *(const float4*)&W[(size_t)bk * Hh + n0 + bc + 4];

    const int NB = K / 16;
    for (int kb = 0; kb < NB; kb++) {
        sA[(ak + 0) * 132 + arow] = va0.x;
        sA[(ak + 1) * 132 + arow] = va0.y;
        sA[(ak + 2) * 132 + arow] = va0.z;
        sA[(ak + 3) * 132 + arow] = va0.w;
        sA[(ak + 4) * 132 + arow] = va1.x;
        sA[(ak + 5) * 132 + arow] = va1.y;
        sA[(ak + 6) * 132 + arow] = va1.z;
        sA[(ak + 7) * 132 + arow] = va1.w;
        *(float4*)&sB[bk * 128 + bc]     = vb0;
        *(float4*)&sB[bk * 128 + bc + 4] = vb1;
        __syncthreads();

        if (kb + 1 < NB) {
            int k0 = (kb + 1) * 16;
            va0 = *(const float4*)&A[(size_t)(m0 + arow) * K + k0 + ak];
            va1 = *(const float4*)&A[(size_t)(m0 + arow) * K + k0 + ak + 4];
            vb0 = *(const float4*)&W[(size_t)(k0 + bk) * Hh + n0 + bc];
            vb1 = *(const float4*)&W[(size_t)(k0 + bk) * Hh + n0 + bc + 4];
        }

#pragma unroll
        for (int kk = 0; kk < 16; kk++) {
            float4 a0 = *(const float4*)&sA[kk * 132 + ty * 8];
            float4 a1 = *(const float4*)&sA[kk * 132 + ty * 8 + 4];
            ulonglong2 b0 = *(const ulonglong2*)&sB[kk * 128 + tx * 8];
            ulonglong2 b1 = *(const ulonglong2*)&sB[kk * 128 + tx * 8 + 4];
            float ar[8] = {a0.x, a0.y, a0.z, a0.w, a1.x, a1.y, a1.z, a1.w};
#pragma unroll
            for (int r = 0; r < 8; r++) {
                ull av = dup2(ar[r]);
                acc[r][0] = fma2(av, b0.x, acc[r][0]);
                acc[r][1] = fma2(av, b0.y, acc[r][1]);
                acc[r][2] = fma2(av, b1.x, acc[r][2]);
                acc[r][3] = fma2(av, b1.y, acc[r][3]);
            }
        }
        __syncthreads();
    }

    float4 bi0 = *(const float4*)&bias[n0 + tx * 8];
    float4 bi1 = *(const float4*)&bias[n0 + tx * 8 + 4];
#pragma unroll
    for (int r = 0; r < 8; r++) {
        float2 u0 = unpack2(acc[r][0]);
        float2 u1 = unpack2(acc[r][1]);
        float2 u2 = unpack2(acc[r][2]);
        float2 u3 = unpack2(acc[r][3]);
        float4 o0, o1;
        o0.x = u0.x + bi0.x; o0.y = u0.y + bi0.y; o0.z = u1.x + bi0.z; o0.w = u1.y + bi0.w;
        o1.x = u2.x + bi1.x; o1.y = u2.y + bi1.y; o1.z = u3.x + bi1.z; o1.w = u3.y + bi1.w;
        size_t base = (size_t)(m0 + ty * 8 + r) * Hh + n0 + tx * 8;
        *(float4*)&out[base]     = o0;
        *(float4*)&out[base + 4] = o1;
    }
}

// ---------------------------------------------------------------------------
// Persistent layer kernel — R2 skeleton + L2-hot hx exchange + fast tanh +
// release/acquire + separate partials region + xp prefetch.
// Grid (8 col-tiles x 16 batch-groups) = 128 CTAs, 256 threads.
// ---------------------------------------------------------------------------
#define SH_STR  514                          // scalar reads: banks {b,b+8,b+16,b+24}
#define RED_STR 66
#define WREG    (16 * RED_STR)               // 1056 floats per warp partials
#define SW_FLOATS  (512 * 64)                // 32768
#define SH_FLOATS  (16 * SH_STR)             // 8224
#define RED_FLOATS (8 * WREG)                // 8448
#define LAYER_SMEM ((SW_FLOATS + SH_FLOATS + RED_FLOATS) * 4)   // ~193 KB

extern __shared__ float s_mem[];

__global__ __launch_bounds__(256, 1) void layer_kernel(
    const float* __restrict__ xp, const float* __restrict__ Wh,
    float* __restrict__ h, float* __restrict__ hx,
    int* __restrict__ bar, int layer)
{
    float* sW   = s_mem;                          // [512][64]
    float* sH   = s_mem + SW_FLOATS;              // [16][514]
    float* sRed = s_mem + SW_FLOATS + SH_FLOATS;  // [8][16][66]

    const int n0 = blockIdx.x * 64;
    const int b0 = blockIdx.y * 16;
    int* cnt = &bar[layer * 16 + blockIdx.y];

    const int tid  = threadIdx.x;
    const int w    = tid >> 5;
    const int lane = tid & 31;
    const int rg   = lane >> 3;          // 4 row groups (of 4 rows)
    const int cg   = lane & 7;           // 8 col groups
    const int kbase = w * 64;
    const int tx = tid & 15;             // epilogue col group of 4
    const int ty = tid >> 4;             // epilogue batch row

    // ---- stage Wh[:, n0:n0+64] once ----
    for (int i = tid; i < 512 * 16; i += 256) {
        int k = i >> 4, c4 = i & 15;
        float4 v = *(const float4*)&Wh[(size_t)k * Hh + n0 + c4 * 4];
        *(float4*)&sW[k * 64 + c4 * 4] = v;
    }

    // ---- t = 0: h0 = tanh(xp0) -> h and hx[0] ----
    {
        size_t base = ((size_t)(b0 + ty) * Tt) * Hh + n0 + tx * 4;
        float4 xv = *(const float4*)&xp[base];
        float4 o;
        o.x = fast_tanh(xv.x); o.y = fast_tanh(xv.y);
        o.z = fast_tanh(xv.z); o.w = fast_tanh(xv.w);
        *(float4*)&h[base] = o;
        __stcg((float4*)&hx[(size_t)(b0 + ty) * Hh + n0 + tx * 4], o);
    }
    __syncthreads();                 // sW staged + h0 stores issued
    if (tid == 0) red_release_add(cnt, 1);

    for (int t = 1; t < Tt; t++) {
        // prefetch xp for this step (independent of the flag)
        size_t obase = (((size_t)(b0 + ty) * Tt) + t) * Hh + n0 + tx * 4;
        float4 xv = *(const float4*)&xp[obase];

        // ---- wait for all 8 producers of h_{t-1} ----
        if (tid == 0) {
            while (ld_acquire(cnt) < 8 * t) { }
        }
        __syncthreads();

        // ---- CTA-cooperative stage of hx[(t-1)&1] rows b0..b0+15 ----
        const float* src = hx + ((size_t)((t - 1) & 1)) * (Bb * Hh);
        float4 sv[8];
#pragma unroll
        for (int j = 0; j < 8; j++) {
            int idx = tid + j * 256;
            int b = idx >> 7, k4 = idx & 127;
            sv[j] = __ldcg((const float4*)&src[(size_t)(b0 + b) * Hh + k4 * 4]);
        }
#pragma unroll
        for (int j = 0; j < 8; j++) {
            int idx = tid + j * 256;
            int b = idx >> 7, k4 = idx & 127;
            float* d = &sH[b * SH_STR + k4 * 4];
            *(float2*)&d[0] = make_float2(sv[j].x, sv[j].y);
            *(float2*)&d[2] = make_float2(sv[j].z, sv[j].w);
        }
        __syncthreads();

        // ---- split-k compute: warp w does k in [kbase, kbase+64) ----
        ull acc[4][4];
#pragma unroll
        for (int i = 0; i < 4; i++)
#pragma unroll
            for (int j = 0; j < 4; j++) acc[i][j] = 0ull;

        const float* hp = &sH[(rg * 4) * SH_STR + kbase];
        const float* wp = &sW[kbase * 64];
#pragma unroll 4
        for (int kk = 0; kk < 64; kk++) {
            ull a0 = dup2(hp[kk]);
            ull a1 = dup2(hp[SH_STR + kk]);
            ull a2 = dup2(hp[2 * SH_STR + kk]);
            ull a3 = dup2(hp[3 * SH_STR + kk]);
            ulonglong2 wlo = *(const ulonglong2*)&wp[kk * 64 + cg * 4];
            ulonglong2 whi = *(const ulonglong2*)&wp[kk * 64 + 32 + cg * 4];
            acc[0][0] = fma2(a0, wlo.x, acc[0][0]); acc[0][1] = fma2(a0, wlo.y, acc[0][1]);
            acc[0][2] = fma2(a0, whi.x, acc[0][2]); acc[0][3] = fma2(a0, whi.y, acc[0][3]);
            acc[1][0] = fma2(a1, wlo.x, acc[1][0]); acc[1][1] = fma2(a1, wlo.y, acc[1][1]);
            acc[1][2] = fma2(a1, whi.x, acc[1][2]); acc[1][3] = fma2(a1, whi.y, acc[1][3]);
            acc[2][0] = fma2(a2, wlo.x, acc[2][0]); acc[2][1] = fma2(a2, wlo.y, acc[2][1]);
            acc[2][2] = fma2(a2, whi.x, acc[2][2]); acc[2][3] = fma2(a2, whi.y, acc[2][3]);
            acc[3][0] = fma2(a3, wlo.x, acc[3][0]); acc[3][1] = fma2(a3, wlo.y, acc[3][1]);
            acc[3][2] = fma2(a3, whi.x, acc[3][2]); acc[3][3] = fma2(a3, whi.y, acc[3][3]);
        }

        // ---- store partials (separate region, no pre-barrier) ----
#pragma unroll
        for (int j = 0; j < 4; j++) {
            float* dst = &sRed[w * WREG + (rg * 4 + j) * RED_STR];
            *(ull*)&dst[cg * 4]          = acc[j][0];
            *(ull*)&dst[cg * 4 + 2]      = acc[j][1];
            *(ull*)&dst[32 + cg * 4]     = acc[j][2];
            *(ull*)&dst[32 + cg * 4 + 2] = acc[j][3];
        }
        __syncthreads();

        // ---- reduce 8 partials, add xp, tanh, store h_t (h + hx) ----
        {
            float2 s0 = make_float2(0.f, 0.f), s1 = make_float2(0.f, 0.f);
            int rbase = ty * RED_STR + tx * 4;
#pragma unroll
            for (int w2 = 0; w2 < 8; w2++) {
                float2 u0 = unpack2(*(const ull*)&sRed[w2 * WREG + rbase]);
                float2 u1 = unpack2(*(const ull*)&sRed[w2 * WREG + rbase + 2]);
                s0.x += u0.x; s0.y += u0.y; s1.x += u1.x; s1.y += u1.y;
            }
            float4 o;
            o.x = fast_tanh(s0.x + xv.x); o.y = fast_tanh(s0.y + xv.y);
            o.z = fast_tanh(s1.x + xv.z); o.w = fast_tanh(s1.y + xv.w);
            *(float4*)&h[obase] = o;
            __stcg((float4*)&hx[((size_t)(t & 1)) * (Bb * Hh)
                                + (size_t)(b0 + ty) * Hh + n0 + tx * 4], o);
        }
        __syncthreads();   // STGs issued before the release below
        if (tid == 0 && t < Tt - 1) red_release_add(cnt, 1);
    }
}

// ---------------------------------------------------------------------------
// Final: out[b] = h[b, T-1, :] @ Wf + bf
// ---------------------------------------------------------------------------
__global__ void final_kernel(const float* __restrict__ h, const float* __restrict__ Wf,
                             const float* __restrict__ bf, float* __restrict__ out)
{
    int b = blockIdx.x;
    const float* row = h + ((size_t)b * Tt + (Tt - 1)) * Hh;
    float s = 0.f;
    for (int j = threadIdx.x; j < Hh; j += 128) s += row[j] * Wf[j];
#pragma unroll
    for (int o = 16; o > 0; o >>= 1) s += __shfl_down_sync(0xffffffffu, s, o);
    __shared__ float ws[4];
    if ((threadIdx.x & 31) == 0) ws[threadIdx.x >> 5] = s;
    __syncthreads();
    if (threadIdx.x == 0) out[b] = ws[0] + ws[1] + ws[2] + ws[3] + bf[0];
}

// ---------------------------------------------------------------------------
extern "C" void kernel_launch(void* const* d_in, const int* in_sizes, int n_in,
                              void* d_out, int out_size)
{
    const float* x   = (const float*)d_in[0];
    const float* Wx0 = (const float*)d_in[1];
    const float* Wh0 = (const float*)d_in[2];
    const float* b0  = (const float*)d_in[3];
    const float* Wx1 = (const float*)d_in[4];
    const float* Wh1 = (const float*)d_in[5];
    const float* b1  = (const float*)d_in[6];
    const float* Wx2 = (const float*)d_in[7];
    const float* Wh2 = (const float*)d_in[8];
    const float* b2  = (const float*)d_in[9];
    const float* Wf  = (const float*)d_in[10];
    const float* bf  = (const float*)d_in[11];
    float* out = (float*)d_out;

    void* p;
    cudaGetSymbolAddress(&p, g_xp);
    float* xp = (float*)p;
    cudaGetSymbolAddress(&p, g_h);
    float* hb = (float*)p;
    cudaGetSymbolAddress(&p, g_hx);
    float* hx = (float*)p;
    cudaGetSymbolAddress(&p, g_bar);
    int* bar = (int*)p;

    cudaFuncSetAttribute(layer_kernel, cudaFuncAttributeMaxDynamicSharedMemorySize, LAYER_SMEM);

    dim3 pgrid(Hh / 128, (Bb * Tt) / 128);   // (4, 512)
    dim3 lgrid(Hh / 64, Bb / 16);            // (8, 16) = 128 CTAs

    zero_bar_kernel<<<1, 64>>>();

    proj_kernel<Dd><<<pgrid, 256>>>(x, Wx0, b0, xp);
    layer_kernel<<<lgrid, 256, LAYER_SMEM>>>(xp, Wh0, hb, hx, bar, 0);

    proj_kernel<Hh><<<pgrid, 256>>>(hb, Wx1, b1, xp);
    layer_kernel<<<lgrid, 256, LAYER_SMEM>>>(xp, Wh1, hb, hx, bar, 1);

    proj_kernel<Hh><<<pgrid, 256>>>(hb, Wx2, b2, xp);
    layer_kernel<<<lgrid, 256, LAYER_SMEM>>>(xp, Wh2, hb, hx, bar, 2);

    final_kernel<<<Bb, 128>>>(hb, Wf, bf, out);
}

// round 7
// speedup vs baseline: 1.5918x; 1.0042x over previous
#include <cuda_runtime.h>
#include <math.h>

#define Bb 256
#define Tt 256
#define Dd 64
#define Hh 512
#define NCT 32                     // cols per CTA tile

typedef unsigned long long ull;

// Scratch (device globals: allocation-free rule).
__device__ float g_xp[(size_t)Bb * Tt * Hh];   // xp buffer A
__device__ float g_xq[(size_t)Bb * Tt * Hh];   // xp buffer B
__device__ float g_hx[2 * Bb * Hh];            // 1MB L2-hot h exchange (double)
__device__ int   g_bar[3 * 8];                 // per (layer, group-of-32) counters

// ---------------- packed dual-fp32 helpers (sm_100+ f32x2) ----------------
__device__ __forceinline__ ull fma2(ull a, ull b, ull c) {
    ull d;
    asm("fma.rn.f32x2 %0, %1, %2, %3;" : "=l"(d) : "l"(a), "l"(b), "l"(c));
    return d;
}
__device__ __forceinline__ ull dup2(float x) {
    ull d;
    asm("mov.b64 %0, {%1, %2};" : "=l"(d) : "f"(x), "f"(x));
    return d;
}
__device__ __forceinline__ float2 unpack2(ull v) {
    float2 r;
    asm("mov.b64 {%0, %1}, %2;" : "=f"(r.x), "=f"(r.y) : "l"(v));
    return r;
}
__device__ __forceinline__ int ld_acquire(const int* p) {
    int v;
    asm volatile("ld.acquire.gpu.global.b32 %0, [%1];" : "=r"(v) : "l"(p));
    return v;
}
__device__ __forceinline__ void red_release_add(int* p, int v) {
    asm volatile("red.release.gpu.global.add.s32 [%0], %1;" :: "l"(p), "r"(v) : "memory");
}
__device__ __forceinline__ float fast_tanh(float x) {
    float ax = fabsf(x);
    float e;
    asm("ex2.approx.f32 %0, %1;" : "=f"(e) : "f"(ax * 2.885390082f));
    float t = 1.0f - __fdividef(2.0f, e + 1.0f);
    return copysignf(t, x);
}

__global__ void zero_bar_kernel() {
    if (threadIdx.x < 24) g_bar[threadIdx.x] = 0;
}

// ---------------------------------------------------------------------------
// Projection GEMM for layer 0 only: out[M,Hh] = A[M,64] @ W[64,Hh] + bias
// Tile 128x128, BK=16, 256 threads, thread tile 8x8 via f32x2.
// ---------------------------------------------------------------------------
template <int K>
__global__ __launch_bounds__(256) void proj_kernel(
    const float* __restrict__ A, const float* __restrict__ W,
    const float* __restrict__ bias, float* __restrict__ out)
{
    __shared__ float sA[16 * 132];
    __shared__ float sB[16 * 128];

    const int n0 = blockIdx.x * 128;
    const int m0 = blockIdx.y * 128;
    const int tid = threadIdx.x;
    const int tx = tid & 15;
    const int ty = tid >> 4;

    const int arow = tid >> 1;
    const int ak   = (tid & 1) * 8;
    const int bk   = tid >> 4;
    const int bc   = (tid & 15) * 8;

    ull acc[8][4];
#pragma unroll
    for (int i = 0; i < 8; i++)
#pragma unroll
        for (int j = 0; j < 4; j++) acc[i][j] = 0ull;

    float4 va0 = *(const float4*)&A[(size_t)(m0 + arow) * K + ak];
    float4 va1 = *(const float4*)&A[(size_t)(m0 + arow) * K + ak + 4];
    float4 vb0 = *(const float4*)&W[(size_t)bk * Hh + n0 + bc];
    float4 vb1 = *(const float4*)&W[(size_t)bk * Hh + n0 + bc + 4];

    const int NB = K / 16;
    for (int kb = 0; kb < NB; kb++) {
        sA[(ak + 0) * 132 + arow] = va0.x;
        sA[(ak + 1) * 132 + arow] = va0.y;
        sA[(ak + 2) * 132 + arow] = va0.z;
        sA[(ak + 3) * 132 + arow] = va0.w;
        sA[(ak + 4) * 132 + arow] = va1.x;
        sA[(ak + 5) * 132 + arow] = va1.y;
        sA[(ak + 6) * 132 + arow] = va1.z;
        sA[(ak + 7) * 132 + arow] = va1.w;
        *(float4*)&sB[bk * 128 + bc]     = vb0;
        *(float4*)&sB[bk * 128 + bc + 4] = vb1;
        __syncthreads();

        if (kb + 1 < NB) {
            int k0 = (kb + 1) * 16;
            va0 = *(const float4*)&A[(size_t)(m0 + arow) * K + k0 + ak];
            va1 = *(const float4*)&A[(size_t)(m0 + arow) * K + k0 + ak + 4];
            vb0 = *(const float4*)&W[(size_t)(k0 + bk) * Hh + n0 + bc];
            vb1 = *(const float4*)&W[(size_t)(k0 + bk) * Hh + n0 + bc + 4];
        }

#pragma unroll
        for (int kk = 0; kk < 16; kk++) {
            float4 a0 = *(const float4*)&sA[kk * 132 + ty * 8];
            float4 a1 = *(const float4*)&sA[kk * 132 + ty * 8 + 4];
            ulonglong2 b0 = *(const ulonglong2*)&sB[kk * 128 + tx * 8];
            ulonglong2 b1 = *(const ulonglong2*)&sB[kk * 128 + tx * 8 + 4];
            float ar[8] = {a0.x, a0.y, a0.z, a0.w, a1.x, a1.y, a1.z, a1.w};
#pragma unroll
            for (int r = 0; r < 8; r++) {
                ull av = dup2(ar[r]);
                acc[r][0] = fma2(av, b0.x, acc[r][0]);
                acc[r][1] = fma2(av, b0.y, acc[r][1]);
                acc[r][2] = fma2(av, b1.x, acc[r][2]);
                acc[r][3] = fma2(av, b1.y, acc[r][3]);
            }
        }
        __syncthreads();
    }

    float4 bi0 = *(const float4*)&bias[n0 + tx * 8];
    float4 bi1 = *(const float4*)&bias[n0 + tx * 8 + 4];
#pragma unroll
    for (int r = 0; r < 8; r++) {
        float2 u0 = unpack2(acc[r][0]);
        float2 u1 = unpack2(acc[r][1]);
        float2 u2 = unpack2(acc[r][2]);
        float2 u3 = unpack2(acc[r][3]);
        float4 o0, o1;
        o0.x = u0.x + bi0.x; o0.y = u0.y + bi0.y; o0.z = u1.x + bi0.z; o0.w = u1.y + bi0.w;
        o1.x = u2.x + bi1.x; o1.y = u2.y + bi1.y; o1.z = u3.x + bi1.z; o1.w = u3.y + bi1.w;
        size_t base = (size_t)(m0 + ty * 8 + r) * Hh + n0 + tx * 8;
        *(float4*)&out[base]     = o0;
        *(float4*)&out[base + 4] = o1;
    }
}

// ---------------------------------------------------------------------------
// Fused persistent layer kernel.
// Grid (16 col-tiles of 32 x 8 groups of 32 rows) = 128 CTAs, 256 threads.
// SMEM: Wh slice [512x32], Wx_next slice [512x32], h tile [32][514], partials.
// Per step: recurrence (split-k 4 x row-half 2) then, after releasing h_t,
// FILLER: next layer's projection for h_{t-1} using the same sH tile.
// ---------------------------------------------------------------------------
#define SH_STR  514
#define RED_STR 34
#define SWH_F   (512 * NCT)             // 16384 floats
#define SH_F    (32 * SH_STR)           // 16448
#define RED_F   (4 * 32 * RED_STR)      // 4352
#define LAYER_SMEM ((2 * SWH_F + SH_F + RED_F) * 4)   // 214272 B

extern __shared__ float s_mem[];

__global__ __launch_bounds__(256, 1) void layer_kernel(
    const float* __restrict__ xp,  const float* __restrict__ Wh,
    const float* __restrict__ Wx,  const float* __restrict__ bnext,
    float* __restrict__ xpo,       float* __restrict__ hx,
    int* __restrict__ bar, int layer)
{
    float* sWh  = s_mem;                       // [512][32]
    float* sWx  = s_mem + SWH_F;               // [512][32]
    float* sH   = s_mem + 2 * SWH_F;           // [32][514]
    float* sRed = s_mem + 2 * SWH_F + SH_F;    // [4][32][34]

    const int n0 = blockIdx.x * NCT;
    const int b0 = blockIdx.y * 32;
    int* cnt = &bar[layer * 8 + blockIdx.y];

    const int tid  = threadIdx.x;
    const int w    = tid >> 5;
    const int lane = tid & 31;
    const int kc   = w >> 1;             // k-chunk 0..3 (128 k each)
    const int rh   = w & 1;              // row half (16 rows)
    const int rg   = lane >> 3;          // row group of 4 within half
    const int cg   = lane & 7;           // col group of 4
    const int kbase = kc * 128;
    const int rbase = rh * 16 + rg * 4;

    const int er = tid >> 3;             // epilogue row 0..31
    const int ec = (tid & 7) * 4;        // epilogue col group

    // ---- stage Wh (and Wx_next) column slices once ----
    for (int i = tid; i < 512 * 8; i += 256) {     // 4096 float4 slots
        int k = i >> 3, c4 = i & 7;
        float4 v = *(const float4*)&Wh[(size_t)k * Hh + n0 + c4 * 4];
        *(float4*)&sWh[k * NCT + c4 * 4] = v;
    }
    if (Wx) {
        for (int i = tid; i < 512 * 8; i += 256) {
            int k = i >> 3, c4 = i & 7;
            float4 v = *(const float4*)&Wx[(size_t)k * Hh + n0 + c4 * 4];
            *(float4*)&sWx[k * NCT + c4 * 4] = v;
        }
    }
    float4 bv = make_float4(0.f, 0.f, 0.f, 0.f);
    if (Wx) bv = *(const float4*)&bnext[n0 + ec];

    // ---- t = 0: h0 = tanh(xp0) -> hx[0] ----
    {
        size_t base = ((size_t)(b0 + er) * Tt) * Hh + n0 + ec;
        float4 xv = *(const float4*)&xp[base];
        float4 o;
        o.x = fast_tanh(xv.x); o.y = fast_tanh(xv.y);
        o.z = fast_tanh(xv.z); o.w = fast_tanh(xv.w);
        __stcg((float4*)&hx[(size_t)(b0 + er) * Hh + n0 + ec], o);
    }
    __syncthreads();                 // weights staged + h0 issued
    if (tid == 0) red_release_add(cnt, 1);

    for (int t = 1; t < Tt; t++) {
        // prefetch xp for this step (independent of the flag)
        size_t obase = (((size_t)(b0 + er) * Tt) + t) * Hh + n0 + ec;
        float4 xv = *(const float4*)&xp[obase];

        // ---- wait for all 16 producers of h_{t-1} ----
        if (tid == 0) {
            while (ld_acquire(cnt) < 16 * t) { }
        }
        __syncthreads();

        // ---- stage h_{t-1}[b0..b0+31, :] from hx ----
        {
            const float* src = hx + ((size_t)((t - 1) & 1)) * (Bb * Hh);
#pragma unroll
            for (int half = 0; half < 2; half++) {
                float4 sv[8];
#pragma unroll
                for (int j = 0; j < 8; j++) {
                    int slot = tid + (half * 8 + j) * 256;
                    int row = slot >> 7, k4 = slot & 127;
                    sv[j] = __ldcg((const float4*)&src[(size_t)(b0 + row) * Hh + k4 * 4]);
                }
#pragma unroll
                for (int j = 0; j < 8; j++) {
                    int slot = tid + (half * 8 + j) * 256;
                    int row = slot >> 7, k4 = slot & 127;
                    float* d = &sH[row * SH_STR + k4 * 4];
                    *(float2*)&d[0] = make_float2(sv[j].x, sv[j].y);
                    *(float2*)&d[2] = make_float2(sv[j].z, sv[j].w);
                }
            }
        }
        __syncthreads();

        // ---- recurrence compute: warp (kc, rh): [16 rows x 32 cols], 128 k ----
        {
            ull a00 = 0, a01 = 0, a10 = 0, a11 = 0,
                a20 = 0, a21 = 0, a30 = 0, a31 = 0;
            const float* hp = &sH[rbase * SH_STR + kbase];
            const float* wp = &sWh[kbase * NCT];
#pragma unroll 8
            for (int kk = 0; kk < 128; kk += 2) {
                float2 h0 = *(const float2*)&hp[kk];
                float2 h1 = *(const float2*)&hp[SH_STR + kk];
                float2 h2 = *(const float2*)&hp[2 * SH_STR + kk];
                float2 h3 = *(const float2*)&hp[3 * SH_STR + kk];
                ulonglong2 wa = *(const ulonglong2*)&wp[kk * NCT + cg * 4];
                ulonglong2 wb = *(const ulonglong2*)&wp[(kk + 1) * NCT + cg * 4];
                ull a;
                a = dup2(h0.x); a00 = fma2(a, wa.x, a00); a01 = fma2(a, wa.y, a01);
                a = dup2(h1.x); a10 = fma2(a, wa.x, a10); a11 = fma2(a, wa.y, a11);
                a = dup2(h2.x); a20 = fma2(a, wa.x, a20); a21 = fma2(a, wa.y, a21);
                a = dup2(h3.x); a30 = fma2(a, wa.x, a30); a31 = fma2(a, wa.y, a31);
                a = dup2(h0.y); a00 = fma2(a, wb.x, a00); a01 = fma2(a, wb.y, a01);
                a = dup2(h1.y); a10 = fma2(a, wb.x, a10); a11 = fma2(a, wb.y, a11);
                a = dup2(h2.y); a20 = fma2(a, wb.x, a20); a21 = fma2(a, wb.y, a21);
                a = dup2(h3.y); a30 = fma2(a, wb.x, a30); a31 = fma2(a, wb.y, a31);
            }
            float* dst = &sRed[kc * (32 * RED_STR) + rbase * RED_STR + cg * 4];
            *(ull*)&dst[0] = a00; *(ull*)&dst[2] = a01;
            *(ull*)&dst[RED_STR] = a10; *(ull*)&dst[RED_STR + 2] = a11;
            *(ull*)&dst[2 * RED_STR] = a20; *(ull*)&dst[2 * RED_STR + 2] = a21;
            *(ull*)&dst[3 * RED_STR] = a30; *(ull*)&dst[3 * RED_STR + 2] = a31;
        }
        __syncthreads();

        // ---- reduce 4 partials, add xp, tanh, store h_t to hx ----
        {
            float2 s0 = make_float2(0.f, 0.f), s1 = make_float2(0.f, 0.f);
            int rb = er * RED_STR + ec;
#pragma unroll
            for (int q = 0; q < 4; q++) {
                float2 u0 = unpack2(*(const ull*)&sRed[q * (32 * RED_STR) + rb]);
                float2 u1 = unpack2(*(const ull*)&sRed[q * (32 * RED_STR) + rb + 2]);
                s0.x += u0.x; s0.y += u0.y; s1.x += u1.x; s1.y += u1.y;
            }
            float4 o;
            o.x = fast_tanh(s0.x + xv.x); o.y = fast_tanh(s0.y + xv.y);
            o.z = fast_tanh(s1.x + xv.z); o.w = fast_tanh(s1.y + xv.w);
            __stcg((float4*)&hx[((size_t)(t & 1)) * (Bb * Hh)
                                + (size_t)(b0 + er) * Hh + n0 + ec], o);
        }
        __syncthreads();                     // all stores issued before release
        if (tid == 0) red_release_add(cnt, 1);

        // ---- FILLER: next layer's projection of h_{t-1} (sH still intact) ----
        if (Wx) {
            ull a00 = 0, a01 = 0, a10 = 0, a11 = 0,
                a20 = 0, a21 = 0, a30 = 0, a31 = 0;
            const float* hp = &sH[rbase * SH_STR + kbase];
            const float* wp = &sWx[kbase * NCT];
#pragma unroll 8
            for (int kk = 0; kk < 128; kk += 2) {
                float2 h0 = *(const float2*)&hp[kk];
                float2 h1 = *(const float2*)&hp[SH_STR + kk];
                float2 h2 = *(const float2*)&hp[2 * SH_STR + kk];
                float2 h3 = *(const float2*)&hp[3 * SH_STR + kk];
                ulonglong2 wa = *(const ulonglong2*)&wp[kk * NCT + cg * 4];
                ulonglong2 wb = *(const ulonglong2*)&wp[(kk + 1) * NCT + cg * 4];
                ull a;
                a = dup2(h0.x); a00 = fma2(a, wa.x, a00); a01 = fma2(a, wa.y, a01);
                a = dup2(h1.x); a10 = fma2(a, wa.x, a10); a11 = fma2(a, wa.y, a11);
                a = dup2(h2.x); a20 = fma2(a, wa.x, a20); a21 = fma2(a, wa.y, a21);
                a = dup2(h3.x); a30 = fma2(a, wa.x, a30); a31 = fma2(a, wa.y, a31);
                a = dup2(h0.y); a00 = fma2(a, wb.x, a00); a01 = fma2(a, wb.y, a01);
                a = dup2(h1.y); a10 = fma2(a, wb.x, a10); a11 = fma2(a, wb.y, a11);
                a = dup2(h2.y); a20 = fma2(a, wb.x, a20); a21 = fma2(a, wb.y, a21);
                a = dup2(h3.y); a30 = fma2(a, wb.x, a30); a31 = fma2(a, wb.y, a31);
            }
            __syncthreads();                 // recurrence reduce done reading sRed
            float* dst = &sRed[kc * (32 * RED_STR) + rbase * RED_STR + cg * 4];
            *(ull*)&dst[0] = a00; *(ull*)&dst[2] = a01;
            *(ull*)&dst[RED_STR] = a10; *(ull*)&dst[RED_STR + 2] = a11;
            *(ull*)&dst[2 * RED_STR] = a20; *(ull*)&dst[2 * RED_STR + 2] = a21;
            *(ull*)&dst[3 * RED_STR] = a30; *(ull*)&dst[3 * RED_STR + 2] = a31;
            __syncthreads();
            float2 s0 = make_float2(0.f, 0.f), s1 = make_float2(0.f, 0.f);
            int rb = er * RED_STR + ec;
#pragma unroll
            for (int q = 0; q < 4; q++) {
                float2 u0 = unpack2(*(const ull*)&sRed[q * (32 * RED_STR) + rb]);
                float2 u1 = unpack2(*(const ull*)&sRed[q * (32 * RED_STR) + rb + 2]);
                s0.x += u0.x; s0.y += u0.y; s1.x += u1.x; s1.y += u1.y;
            }
            float4 o;
            o.x = s0.x + bv.x; o.y = s0.y + bv.y;
            o.z = s1.x + bv.z; o.w = s1.y + bv.w;
            *(float4*)&xpo[(((size_t)(b0 + er) * Tt) + (t - 1)) * Hh + n0 + ec] = o;
        }
    }

    // ---- tail: projection of h_{Tt-1} ----
    if (Wx) {
        if (tid == 0) {
            while (ld_acquire(cnt) < 16 * Tt) { }
        }
        __syncthreads();
        {
            const float* src = hx + ((size_t)((Tt - 1) & 1)) * (Bb * Hh);
#pragma unroll
            for (int half = 0; half < 2; half++) {
                float4 sv[8];
#pragma unroll
                for (int j = 0; j < 8; j++) {
                    int slot = tid + (half * 8 + j) * 256;
                    int row = slot >> 7, k4 = slot & 127;
                    sv[j] = __ldcg((const float4*)&src[(size_t)(b0 + row) * Hh + k4 * 4]);
                }
#pragma unroll
                for (int j = 0; j < 8; j++) {
                    int slot = tid + (half * 8 + j) * 256;
                    int row = slot >> 7, k4 = slot & 127;
                    float* d = &sH[row * SH_STR + k4 * 4];
                    *(float2*)&d[0] = make_float2(sv[j].x, sv[j].y);
                    *(float2*)&d[2] = make_float2(sv[j].z, sv[j].w);
                }
            }
        }
        __syncthreads();
        {
            ull a00 = 0, a01 = 0, a10 = 0, a11 = 0,
                a20 = 0, a21 = 0, a30 = 0, a31 = 0;
            const float* hp = &sH[rbase * SH_STR + kbase];
            const float* wp = &sWx[kbase * NCT];
#pragma unroll 8
            for (int kk = 0; kk < 128; kk += 2) {
                float2 h0 = *(const float2*)&hp[kk];
                float2 h1 = *(const float2*)&hp[SH_STR + kk];
                float2 h2 = *(const float2*)&hp[2 * SH_STR + kk];
                float2 h3 = *(const float2*)&hp[3 * SH_STR + kk];
                ulonglong2 wa = *(const ulonglong2*)&wp[kk * NCT + cg * 4];
                ulonglong2 wb = *(const ulonglong2*)&wp[(kk + 1) * NCT + cg * 4];
                ull a;
                a = dup2(h0.x); a00 = fma2(a, wa.x, a00); a01 = fma2(a, wa.y, a01);
                a = dup2(h1.x); a10 = fma2(a, wa.x, a10); a11 = fma2(a, wa.y, a11);
                a = dup2(h2.x); a20 = fma2(a, wa.x, a20); a21 = fma2(a, wa.y, a21);
                a = dup2(h3.x); a30 = fma2(a, wa.x, a30); a31 = fma2(a, wa.y, a31);
                a = dup2(h0.y); a00 = fma2(a, wb.x, a00); a01 = fma2(a, wb.y, a01);
                a = dup2(h1.y); a10 = fma2(a, wb.x, a10); a11 = fma2(a, wb.y, a11);
                a = dup2(h2.y); a20 = fma2(a, wb.x, a20); a21 = fma2(a, wb.y, a21);
                a = dup2(h3.y); a30 = fma2(a, wb.x, a30); a31 = fma2(a, wb.y, a31);
            }
            float* dst = &sRed[kc * (32 * RED_STR) + rbase * RED_STR + cg * 4];
            *(ull*)&dst[0] = a00; *(ull*)&dst[2] = a01;
            *(ull*)&dst[RED_STR] = a10; *(ull*)&dst[RED_STR + 2] = a11;
            *(ull*)&dst[2 * RED_STR] = a20; *(ull*)&dst[2 * RED_STR + 2] = a21;
            *(ull*)&dst[3 * RED_STR] = a30; *(ull*)&dst[3 * RED_STR + 2] = a31;
            __syncthreads();
            float2 s0 = make_float2(0.f, 0.f), s1 = make_float2(0.f, 0.f);
            int rb = er * RED_STR + ec;
#pragma unroll
            for (int q = 0; q < 4; q++) {
                float2 u0 = unpack2(*(const ull*)&sRed[q * (32 * RED_STR) + rb]);
                float2 u1 = unpack2(*(const ull*)&sRed[q * (32 * RED_STR) + rb + 2]);
                s0.x += u0.x; s0.y += u0.y; s1.x += u1.x; s1.y += u1.y;
            }
            float4 o;
            o.x = s0.x + bv.x; o.y = s0.y + bv.y;
            o.z = s1.x + bv.z; o.w = s1.y + bv.w;
            *(float4*)&xpo[(((size_t)(b0 + er) * Tt) + (Tt - 1)) * Hh + n0 + ec] = o;
        }
    }
}

// ---------------------------------------------------------------------------
// Final: out[b] = hx[1][b,:] @ Wf + bf   (h at t=255, parity 1)
// ---------------------------------------------------------------------------
__global__ void final_kernel(const float* __restrict__ hx, const float* __restrict__ Wf,
                             const float* __restrict__ bf, float* __restrict__ out)
{
    int b = blockIdx.x;
    const float* row = hx + (size_t)(Bb * Hh) + (size_t)b * Hh;
    float s = 0.f;
    for (int j = threadIdx.x; j < Hh; j += 128) s += row[j] * Wf[j];
#pragma unroll
    for (int o = 16; o > 0; o >>= 1) s += __shfl_down_sync(0xffffffffu, s, o);
    __shared__ float ws[4];
    if ((threadIdx.x & 31) == 0) ws[threadIdx.x >> 5] = s;
    __syncthreads();
    if (threadIdx.x == 0) out[b] = ws[0] + ws[1] + ws[2] + ws[3] + bf[0];
}

// ---------------------------------------------------------------------------
extern "C" void kernel_launch(void* const* d_in, const int* in_sizes, int n_in,
                              void* d_out, int out_size)
{
    const float* x    = (const float*)d_in[0];
    const float* Wx0  = (const float*)d_in[1];
    const float* Wh0  = (const float*)d_in[2];
    const float* bi0  = (const float*)d_in[3];
    const float* Wx1  = (const float*)d_in[4];
    const float* Wh1  = (const float*)d_in[5];
    const float* bi1  = (const float*)d_in[6];
    const float* Wx2  = (const float*)d_in[7];
    const float* Wh2  = (const float*)d_in[8];
    const float* bi2  = (const float*)d_in[9];
    const float* Wf   = (const float*)d_in[10];
    const float* bf   = (const float*)d_in[11];
    float* out = (float*)d_out;

    void* p;
    cudaGetSymbolAddress(&p, g_xp);
    float* xpA = (float*)p;
    cudaGetSymbolAddress(&p, g_xq);
    float* xpB = (float*)p;
    cudaGetSymbolAddress(&p, g_hx);
    float* hx = (float*)p;
    cudaGetSymbolAddress(&p, g_bar);
    int* bar = (int*)p;

    cudaFuncSetAttribute(layer_kernel, cudaFuncAttributeMaxDynamicSharedMemorySize, LAYER_SMEM);

    dim3 pgrid(Hh / 128, (Bb * Tt) / 128);   // (4, 512)
    dim3 lgrid(Hh / NCT, Bb / 32);           // (16, 8) = 128 CTAs

    zero_bar_kernel<<<1, 32>>>();

    // layer 0 input projection (K=64)
    proj_kernel<Dd><<<pgrid, 256>>>(x, Wx0, bi0, xpA);
    // layer 0 recurrence + fused projection for layer 1
    layer_kernel<<<lgrid, 256, LAYER_SMEM>>>(xpA, Wh0, Wx1, bi1, xpB, hx, bar, 0);
    // layer 1 recurrence + fused projection for layer 2
    layer_kernel<<<lgrid, 256, LAYER_SMEM>>>(xpB, Wh1, Wx2, bi2, xpA, hx, bar, 1);
    // layer 2 recurrence only
    layer_kernel<<<lgrid, 256, LAYER_SMEM>>>(xpA, Wh2, nullptr, nullptr, nullptr, hx, bar, 2);
    // head
    final_kernel<<<Bb, 128>>>(hx, Wf, bf, out);
}